// round 5
// baseline (speedup 1.0000x reference)
#include <cuda_runtime.h>
#include <cuda_fp16.h>
#include <mma.h>
#include <stdint.h>

using namespace nvcuda;

#define N_NODES_MAX 100000
#define E_MAX       3200000
#define F           128

// ---------------- device scratch (static allocation only) ----------------
__device__ int     g_is64;
__device__ int     g_deg[N_NODES_MAX];
__device__ float   g_dinv[N_NODES_MAX];
__device__ int     g_rowptr[N_NODES_MAX + 1];
__device__ int     g_cursor[N_NODES_MAX];
__device__ int     g_adj[E_MAX];
__device__ __half  g_w16[F * F];                    // fp16 weight, 32 KB
__device__ __half2 g_sh[(size_t)N_NODES_MAX * 64];  // fp16 UNSCALED support, 25.6 MB

__device__ __forceinline__ int get_idx(const void* ei, size_t pos) {
    if (g_is64) return (int)((const long long*)ei)[pos];
    return ((const int*)ei)[pos];
}

// ---------------- 1. prep: detect dtype + init deg + convert W ----------------
__global__ void prep_kernel(const unsigned int* __restrict__ raw,
                            const float* __restrict__ w, int n) {
    int i = blockIdx.x * blockDim.x + threadIdx.x;
    if (i < n) g_deg[i] = 1;                 // self loop
    if (i < F * F) g_w16[i] = __float2half_rn(w[i]);

    if (blockIdx.x == 0) {
        __shared__ int nonzero;
        if (threadIdx.x == 0) nonzero = 0;
        __syncthreads();
        int local = 0;
        for (int k = threadIdx.x; k < 2048; k += blockDim.x)
            if (raw[2 * k + 1] != 0u) local = 1;
        if (local) atomicOr(&nonzero, 1);
        __syncthreads();
        if (threadIdx.x == 0) g_is64 = (nonzero == 0) ? 1 : 0;
    }
}

// ---------------- 2. degree ----------------
__global__ void degree_kernel(const void* __restrict__ ei, int e) {
    int i = blockIdx.x * blockDim.x + threadIdx.x;
    if (i < e) atomicAdd(&g_deg[get_idx(ei, i)], 1);
}

// ---------------- 3. single-block chunked scan: rowptr/cursor/dinv ----------
__global__ void scan_all_kernel(int n, int e) {
    __shared__ int wsums[32];
    __shared__ int carry_s;
    int tid  = threadIdx.x;
    int wid  = tid >> 5;
    int lane = tid & 31;
    if (tid == 0) carry_s = 0;
    __syncthreads();

    for (int base = 0; base < n; base += 4096) {
        int v[4];
#pragma unroll
        for (int j = 0; j < 4; j++) {
            int idx = base + tid * 4 + j;
            if (idx < n) {
                int d = g_deg[idx];
                v[j] = d - 1;
                g_dinv[idx] = rsqrtf((float)d);
            } else v[j] = 0;
        }
        int s = v[0] + v[1] + v[2] + v[3];
        int x = s;
#pragma unroll
        for (int o = 1; o < 32; o <<= 1) {
            int y = __shfl_up_sync(0xffffffffu, x, o);
            if (lane >= o) x += y;
        }
        if (lane == 31) wsums[wid] = x;
        __syncthreads();
        if (tid < 32) {
            int wv = wsums[tid];
#pragma unroll
            for (int o = 1; o < 32; o <<= 1) {
                int y = __shfl_up_sync(0xffffffffu, wv, o);
                if (tid >= o) wv += y;
            }
            wsums[tid] = wv;  // inclusive
        }
        __syncthreads();

        int carry = carry_s;
        int excl = x - s + ((wid > 0) ? wsums[wid - 1] : 0) + carry;
        int run = excl;
#pragma unroll
        for (int j = 0; j < 4; j++) {
            int idx = base + tid * 4 + j;
            if (idx < n) { g_rowptr[idx] = run; g_cursor[idx] = run; }
            run += v[j];
        }
        __syncthreads();           // everyone has consumed old carry
        if (tid == 1023) carry_s = run;
        __syncthreads();
    }
    if (tid == 0) g_rowptr[n] = e;
}

// ---------------- 4. tensor-core GEMM: g_sh = fp16(x @ W)  (slot 4) --------
// x split hi+lo fp16 (two MMA passes). B loaded straight from g_w16 (global).
#define APAD 136   // half stride with padding

__global__ __launch_bounds__(256) void gemm_tc_kernel(
    const float* __restrict__ x, int n)
{
    extern __shared__ char smem[];
    __half* Ahi = (__half*)smem;                 // [128][APAD]
    __half* Alo = Ahi + 128 * APAD;
    float*  Cs  = (float*)smem;                  // epilogue reuse [128][APAD]

    int tid = threadIdx.x;
    int block_row = blockIdx.x * 128;
    int wid  = tid >> 5;
    int wm   = wid & 3;     // 0..3 -> M offset wm*32
    int wn   = wid >> 2;    // 0..1 -> N offset wn*64
    int lane = tid & 31;

    // load + hi/lo convert: 256 threads cover 128 rows x 128 cols (float4 each)
    int c4 = lane * 4;
    int r0 = tid >> 5;
#pragma unroll
    for (int i = 0; i < 16; i++) {
        int r  = r0 + i * 8;    // 0..127 exactly once
        int gr = block_row + r;
        float4 v = make_float4(0.f, 0.f, 0.f, 0.f);
        if (gr < n) v = *(const float4*)(x + (size_t)gr * F + c4);
        __half h0 = __float2half_rn(v.x), h1 = __float2half_rn(v.y);
        __half h2 = __float2half_rn(v.z), h3 = __float2half_rn(v.w);
        Ahi[r * APAD + c4 + 0] = h0;
        Ahi[r * APAD + c4 + 1] = h1;
        Ahi[r * APAD + c4 + 2] = h2;
        Ahi[r * APAD + c4 + 3] = h3;
        Alo[r * APAD + c4 + 0] = __float2half_rn(v.x - __half2float(h0));
        Alo[r * APAD + c4 + 1] = __float2half_rn(v.y - __half2float(h1));
        Alo[r * APAD + c4 + 2] = __float2half_rn(v.z - __half2float(h2));
        Alo[r * APAD + c4 + 3] = __float2half_rn(v.w - __half2float(h3));
    }
    __syncthreads();

    wmma::fragment<wmma::accumulator, 16, 16, 16, float> acc[2][4];
#pragma unroll
    for (int mi = 0; mi < 2; mi++)
#pragma unroll
        for (int ni = 0; ni < 4; ni++) wmma::fill_fragment(acc[mi][ni], 0.0f);

#pragma unroll
    for (int k = 0; k < 8; k++) {
        wmma::fragment<wmma::matrix_b, 16, 16, 16, __half, wmma::row_major> bf[4];
#pragma unroll
        for (int ni = 0; ni < 4; ni++)
            wmma::load_matrix_sync(bf[ni], g_w16 + (k * 16) * F + wn * 64 + ni * 16, F);
#pragma unroll
        for (int pass = 0; pass < 2; pass++) {
            const __half* A = pass ? Alo : Ahi;
            wmma::fragment<wmma::matrix_a, 16, 16, 16, __half, wmma::row_major> af[2];
#pragma unroll
            for (int mi = 0; mi < 2; mi++)
                wmma::load_matrix_sync(af[mi], A + (wm * 32 + mi * 16) * APAD + k * 16, APAD);
#pragma unroll
            for (int mi = 0; mi < 2; mi++)
#pragma unroll
                for (int ni = 0; ni < 4; ni++)
                    wmma::mma_sync(acc[mi][ni], af[mi], bf[ni], acc[mi][ni]);
        }
    }
    __syncthreads();   // done reading A smem; reuse as float C

#pragma unroll
    for (int mi = 0; mi < 2; mi++)
#pragma unroll
        for (int ni = 0; ni < 4; ni++)
            wmma::store_matrix_sync(Cs + (wm * 32 + mi * 16) * APAD + wn * 64 + ni * 16,
                                    acc[mi][ni], APAD, wmma::mem_row_major);
    __syncthreads();

    // coalesced epilogue: each warp owns 16 rows; lanes cover columns
    int wr = wid * 16;
#pragma unroll
    for (int rr = 0; rr < 16; rr++) {
        int r  = wr + rr;
        int gr = block_row + r;
        if (gr < n) {
            const float2* crow = (const float2*)(Cs + r * APAD);
            __half2* orow = g_sh + (size_t)gr * 64;
            float2 v0 = crow[lane];
            float2 v1 = crow[lane + 32];
            orow[lane]      = __floats2half2_rn(v0.x, v0.y);
            orow[lane + 32] = __floats2half2_rn(v1.x, v1.y);
        }
    }
}

// ---------------- 5. scatter (CSR adjacency fill) ----------------
__global__ void scatter_kernel(const void* __restrict__ ei, int e) {
    int i = blockIdx.x * blockDim.x + threadIdx.x;
    if (i < e) {
        int src = get_idx(ei, i);
        int dst = get_idx(ei, (size_t)e + i);
        int pos = atomicAdd(&g_cursor[src], 1);
        g_adj[pos] = dst;
    }
}

// ---------------- 6. aggregation: warp/node, dinv[col] applied on the fly ---
__global__ void aggregate_kernel(float* __restrict__ out,
                                 const float* __restrict__ bias, int n)
{
    int warp = (blockIdx.x * blockDim.x + threadIdx.x) >> 5;
    int lane = threadIdx.x & 31;
    if (warp >= n) return;

    const uint2* sv = (const uint2*)g_sh;   // row = 32 uint2 (256 B)

    float ds = g_dinv[warp];
    uint2 p = __ldg(&sv[(size_t)warp * 32 + lane]);   // self loop
    float2 f0 = __half22float2(*(__half2*)&p.x), f1 = __half22float2(*(__half2*)&p.y);
    float4 acc = make_float4(f0.x * ds, f0.y * ds, f1.x * ds, f1.y * ds);

    int j   = g_rowptr[warp];
    int end = g_rowptr[warp + 1];

    for (; j + 3 < end; j += 4) {
        int c0 = g_adj[j + 0];
        int c1 = g_adj[j + 1];
        int c2 = g_adj[j + 2];
        int c3 = g_adj[j + 3];
        float d0 = __ldg(&g_dinv[c0]);
        float d1 = __ldg(&g_dinv[c1]);
        float d2 = __ldg(&g_dinv[c2]);
        float d3 = __ldg(&g_dinv[c3]);
        uint2 p0 = __ldg(&sv[(size_t)c0 * 32 + lane]);
        uint2 p1 = __ldg(&sv[(size_t)c1 * 32 + lane]);
        uint2 p2 = __ldg(&sv[(size_t)c2 * 32 + lane]);
        uint2 p3 = __ldg(&sv[(size_t)c3 * 32 + lane]);
        float2 q0 = __half22float2(*(__half2*)&p0.x), q1 = __half22float2(*(__half2*)&p0.y);
        float2 q2 = __half22float2(*(__half2*)&p1.x), q3 = __half22float2(*(__half2*)&p1.y);
        float2 q4 = __half22float2(*(__half2*)&p2.x), q5 = __half22float2(*(__half2*)&p2.y);
        float2 q6 = __half22float2(*(__half2*)&p3.x), q7 = __half22float2(*(__half2*)&p3.y);
        acc.x += q0.x * d0 + q2.x * d1 + q4.x * d2 + q6.x * d3;
        acc.y += q0.y * d0 + q2.y * d1 + q4.y * d2 + q6.y * d3;
        acc.z += q1.x * d0 + q3.x * d1 + q5.x * d2 + q7.x * d3;
        acc.w += q1.y * d0 + q3.y * d1 + q5.y * d2 + q7.y * d3;
    }
    for (; j < end; j++) {
        int c = g_adj[j];
        float dc = __ldg(&g_dinv[c]);
        uint2 pv = __ldg(&sv[(size_t)c * 32 + lane]);
        float2 q0 = __half22float2(*(__half2*)&pv.x), q1 = __half22float2(*(__half2*)&pv.y);
        acc.x += q0.x * dc; acc.y += q0.y * dc;
        acc.z += q1.x * dc; acc.w += q1.y * dc;
    }

    float4 b = ((const float4*)bias)[lane];
    float4 o;
    o.x = acc.x * ds + b.x;
    o.y = acc.y * ds + b.y;
    o.z = acc.z * ds + b.z;
    o.w = acc.w * ds + b.w;
    ((float4*)out)[(size_t)warp * 32 + lane] = o;
}

// ---------------- launch ----------------
extern "C" void kernel_launch(void* const* d_in, const int* in_sizes, int n_in,
                              void* d_out, int out_size)
{
    const float* x    = (const float*)d_in[0];
    const void*  ei   = d_in[1];
    const float* w    = (const float*)d_in[2];
    const float* bias = (const float*)d_in[3];
    float*       out  = (float*)d_out;

    int n = in_sizes[0] / F;
    int e = in_sizes[1] / 2;

    // slot 1
    prep_kernel<<<(n + 255) / 256, 256>>>((const unsigned int*)ei, w, n);
    // slot 2
    degree_kernel<<<(e + 255) / 256, 256>>>(ei, e);
    // slot 3
    scan_all_kernel<<<1, 1024>>>(n, e);
    // slot 4  (ncu profiles this one)
    size_t gemm_smem = (size_t)2 * 128 * APAD * sizeof(__half);  // 69632
    cudaFuncSetAttribute(gemm_tc_kernel,
                         cudaFuncAttributeMaxDynamicSharedMemorySize,
                         (int)gemm_smem);
    gemm_tc_kernel<<<(n + 127) / 128, 256, gemm_smem>>>(x, n);
    // slot 5
    scatter_kernel<<<(e + 255) / 256, 256>>>(ei, e);
    // slot 6
    int agg_blocks = (n * 32 + 255) / 256;
    aggregate_kernel<<<agg_blocks, 256>>>(out, bias, n);
}

// round 6
// speedup vs baseline: 1.1403x; 1.1403x over previous
#include <cuda_runtime.h>
#include <cuda_fp16.h>
#include <mma.h>
#include <stdint.h>

using namespace nvcuda;

#define N_NODES_MAX 100000
#define E_MAX       3200000
#define F           128

// ---------------- device scratch (static allocation only) ----------------
__device__ int     g_is64;
__device__ int     g_deg[N_NODES_MAX];
__device__ float   g_dinv[N_NODES_MAX];
__device__ int     g_rowptr[N_NODES_MAX + 1];
__device__ int     g_cursor[N_NODES_MAX];
__device__ int     g_adj[E_MAX];
__device__ __half  g_w16[F * F];                    // fp16 weight, 32 KB
__device__ __half2 g_sh[(size_t)N_NODES_MAX * 64];  // fp16 dinv-scaled support, 25.6 MB

__device__ __forceinline__ int get_idx(const void* ei, size_t pos) {
    if (g_is64) return (int)((const long long*)ei)[pos];
    return ((const int*)ei)[pos];
}

// ---------------- 1. prep: detect dtype + init deg + convert W ----------------
__global__ void prep_kernel(const unsigned int* __restrict__ raw,
                            const float* __restrict__ w, int n) {
    int i = blockIdx.x * blockDim.x + threadIdx.x;
    if (i < n) g_deg[i] = 1;                 // self loop
    if (i < F * F) g_w16[i] = __float2half_rn(w[i]);

    if (blockIdx.x == 0) {
        __shared__ int nonzero;
        if (threadIdx.x == 0) nonzero = 0;
        __syncthreads();
        int local = 0;
        for (int k = threadIdx.x; k < 2048; k += blockDim.x)
            if (raw[2 * k + 1] != 0u) local = 1;
        if (local) atomicOr(&nonzero, 1);
        __syncthreads();
        if (threadIdx.x == 0) g_is64 = (nonzero == 0) ? 1 : 0;
    }
}

// ---------------- 2. degree ----------------
__global__ void degree_kernel(const void* __restrict__ ei, int e) {
    int i = blockIdx.x * blockDim.x + threadIdx.x;
    if (i < e) atomicAdd(&g_deg[get_idx(ei, i)], 1);
}

// ---------------- 3. single-block chunked scan: rowptr/cursor/dinv ----------
__global__ void scan_all_kernel(int n, int e) {
    __shared__ int wsums[32];
    __shared__ int carry_s;
    int tid  = threadIdx.x;
    int wid  = tid >> 5;
    int lane = tid & 31;
    if (tid == 0) carry_s = 0;
    __syncthreads();

    for (int base = 0; base < n; base += 4096) {
        int v[4];
#pragma unroll
        for (int j = 0; j < 4; j++) {
            int idx = base + tid * 4 + j;
            if (idx < n) {
                int d = g_deg[idx];
                v[j] = d - 1;
                g_dinv[idx] = rsqrtf((float)d);
            } else v[j] = 0;
        }
        int s = v[0] + v[1] + v[2] + v[3];
        int x = s;
#pragma unroll
        for (int o = 1; o < 32; o <<= 1) {
            int y = __shfl_up_sync(0xffffffffu, x, o);
            if (lane >= o) x += y;
        }
        if (lane == 31) wsums[wid] = x;
        __syncthreads();
        if (tid < 32) {
            int wv = wsums[tid];
#pragma unroll
            for (int o = 1; o < 32; o <<= 1) {
                int y = __shfl_up_sync(0xffffffffu, wv, o);
                if (tid >= o) wv += y;
            }
            wsums[tid] = wv;  // inclusive
        }
        __syncthreads();

        int carry = carry_s;
        int excl = x - s + ((wid > 0) ? wsums[wid - 1] : 0) + carry;
        int run = excl;
#pragma unroll
        for (int j = 0; j < 4; j++) {
            int idx = base + tid * 4 + j;
            if (idx < n) { g_rowptr[idx] = run; g_cursor[idx] = run; }
            run += v[j];
        }
        __syncthreads();
        if (tid == 1023) carry_s = run;
        __syncthreads();
    }
    if (tid == 0) g_rowptr[n] = e;
}

// ---------------- 4. tensor-core GEMM: g_sh = fp16((x @ W) * dinv[row]) -----
// x split hi+lo fp16 (two MMA passes). B resident in smem. 2 blocks/SM.
#define APAD 136   // half stride with padding

__global__ __launch_bounds__(256, 2) void gemm_tc_kernel(
    const float* __restrict__ x, int n)
{
    extern __shared__ char smem[];
    __half* Ahi = (__half*)smem;                 // [128][APAD]
    __half* Alo = Ahi + 128 * APAD;
    __half* Bs  = Alo + 128 * APAD;              // [128][APAD]
    float*  Cs  = (float*)smem;                  // epilogue reuse of Ahi+Alo

    int tid = threadIdx.x;
    int lane = tid & 31;
    int wid  = tid >> 5;
    int wm   = wid & 3;     // 0..3 -> M offset wm*32
    int wn   = wid >> 2;    // 0..1 -> N offset wn*64
    int block_row = blockIdx.x * 128;

    // load B into smem once: thread -> (row=tid>>1, colhalf=(tid&1)*64)
    {
        int r  = tid >> 1;
        int cb = (tid & 1) * 64;
        const uint4* src = (const uint4*)(g_w16 + r * F + cb);   // 8 x uint4
        uint4* dst = (uint4*)(Bs + r * APAD + cb);
#pragma unroll
        for (int k = 0; k < 8; k++) dst[k] = src[k];
    }

    // load A + hi/lo convert: 256 threads cover 128 rows x 128 cols
    int c4 = lane * 4;
#pragma unroll
    for (int i = 0; i < 16; i++) {
        int r  = wid + i * 8;    // 0..127 exactly once
        int gr = block_row + r;
        float4 v = make_float4(0.f, 0.f, 0.f, 0.f);
        if (gr < n) v = *(const float4*)(x + (size_t)gr * F + c4);
        __half h0 = __float2half_rn(v.x), h1 = __float2half_rn(v.y);
        __half h2 = __float2half_rn(v.z), h3 = __float2half_rn(v.w);
        Ahi[r * APAD + c4 + 0] = h0;
        Ahi[r * APAD + c4 + 1] = h1;
        Ahi[r * APAD + c4 + 2] = h2;
        Ahi[r * APAD + c4 + 3] = h3;
        Alo[r * APAD + c4 + 0] = __float2half_rn(v.x - __half2float(h0));
        Alo[r * APAD + c4 + 1] = __float2half_rn(v.y - __half2float(h1));
        Alo[r * APAD + c4 + 2] = __float2half_rn(v.z - __half2float(h2));
        Alo[r * APAD + c4 + 3] = __float2half_rn(v.w - __half2float(h3));
    }
    __syncthreads();

    wmma::fragment<wmma::accumulator, 16, 16, 16, float> acc[2][4];
#pragma unroll
    for (int mi = 0; mi < 2; mi++)
#pragma unroll
        for (int ni = 0; ni < 4; ni++) wmma::fill_fragment(acc[mi][ni], 0.0f);

#pragma unroll
    for (int k = 0; k < 8; k++) {
        wmma::fragment<wmma::matrix_b, 16, 16, 16, __half, wmma::row_major> bf[4];
#pragma unroll
        for (int ni = 0; ni < 4; ni++)
            wmma::load_matrix_sync(bf[ni], Bs + (k * 16) * APAD + wn * 64 + ni * 16, APAD);
#pragma unroll
        for (int pass = 0; pass < 2; pass++) {
            const __half* A = pass ? Alo : Ahi;
            wmma::fragment<wmma::matrix_a, 16, 16, 16, __half, wmma::row_major> af[2];
#pragma unroll
            for (int mi = 0; mi < 2; mi++)
                wmma::load_matrix_sync(af[mi], A + (wm * 32 + mi * 16) * APAD + k * 16, APAD);
#pragma unroll
            for (int mi = 0; mi < 2; mi++)
#pragma unroll
                for (int ni = 0; ni < 4; ni++)
                    wmma::mma_sync(acc[mi][ni], af[mi], bf[ni], acc[mi][ni]);
        }
    }
    __syncthreads();   // done reading A smem; reuse as float C

#pragma unroll
    for (int mi = 0; mi < 2; mi++)
#pragma unroll
        for (int ni = 0; ni < 4; ni++)
            wmma::store_matrix_sync(Cs + (wm * 32 + mi * 16) * APAD + wn * 64 + ni * 16,
                                    acc[mi][ni], APAD, wmma::mem_row_major);
    __syncthreads();

    // coalesced epilogue: warp owns 16 rows; scale row by dinv; fp16 store
    int wr = wid * 16;
#pragma unroll
    for (int rr = 0; rr < 16; rr++) {
        int r  = wr + rr;
        int gr = block_row + r;
        if (gr < n) {
            float d = g_dinv[gr];
            const float2* crow = (const float2*)(Cs + r * APAD);
            __half2* orow = g_sh + (size_t)gr * 64;
            float2 v0 = crow[lane];
            float2 v1 = crow[lane + 32];
            orow[lane]      = __floats2half2_rn(v0.x * d, v0.y * d);
            orow[lane + 32] = __floats2half2_rn(v1.x * d, v1.y * d);
        }
    }
}

// ---------------- 5. scatter (CSR adjacency fill) ----------------
__global__ void scatter_kernel(const void* __restrict__ ei, int e) {
    int i = blockIdx.x * blockDim.x + threadIdx.x;
    if (i < e) {
        int src = get_idx(ei, i);
        int dst = get_idx(ei, (size_t)e + i);
        int pos = atomicAdd(&g_cursor[src], 1);
        g_adj[pos] = dst;
    }
}

// ---------------- 6. aggregation: warp/node, half-warp split, 128-bit loads -
__global__ void aggregate_kernel(float* __restrict__ out,
                                 const float* __restrict__ bias, int n)
{
    int warp = (blockIdx.x * blockDim.x + threadIdx.x) >> 5;
    int lane = threadIdx.x & 31;
    if (warp >= n) return;
    int half = lane >> 4;    // 0 or 1: even/odd neighbor stream
    int hl   = lane & 15;    // column quad 0..15 (16 B each)

    const uint4* sv = (const uint4*)g_sh;   // row = 16 uint4 (256 B)

    float acc[8];
#pragma unroll
    for (int k = 0; k < 8; k++) acc[k] = 0.0f;

    // self loop handled by half 1 (half 0 does the final write)
    if (half) {
        uint4 p = __ldg(&sv[(size_t)warp * 16 + hl]);
        __half2 h0 = *(__half2*)&p.x, h1 = *(__half2*)&p.y;
        __half2 h2 = *(__half2*)&p.z, h3 = *(__half2*)&p.w;
        float2 f0 = __half22float2(h0), f1 = __half22float2(h1);
        float2 f2 = __half22float2(h2), f3 = __half22float2(h3);
        acc[0] += f0.x; acc[1] += f0.y; acc[2] += f1.x; acc[3] += f1.y;
        acc[4] += f2.x; acc[5] += f2.y; acc[6] += f3.x; acc[7] += f3.y;
    }

    int j   = g_rowptr[warp];
    int end = g_rowptr[warp + 1];

    // unrolled: each half-warp takes 2 edges per 4-edge chunk
    for (; j + 4 <= end; j += 4) {
        int c0 = g_adj[j + half];
        int c1 = g_adj[j + half + 2];
        uint4 p0 = __ldg(&sv[(size_t)c0 * 16 + hl]);
        uint4 p1 = __ldg(&sv[(size_t)c1 * 16 + hl]);
        {
            __half2 h0 = *(__half2*)&p0.x, h1 = *(__half2*)&p0.y;
            __half2 h2 = *(__half2*)&p0.z, h3 = *(__half2*)&p0.w;
            float2 f0 = __half22float2(h0), f1 = __half22float2(h1);
            float2 f2 = __half22float2(h2), f3 = __half22float2(h3);
            acc[0] += f0.x; acc[1] += f0.y; acc[2] += f1.x; acc[3] += f1.y;
            acc[4] += f2.x; acc[5] += f2.y; acc[6] += f3.x; acc[7] += f3.y;
        }
        {
            __half2 h0 = *(__half2*)&p1.x, h1 = *(__half2*)&p1.y;
            __half2 h2 = *(__half2*)&p1.z, h3 = *(__half2*)&p1.w;
            float2 f0 = __half22float2(h0), f1 = __half22float2(h1);
            float2 f2 = __half22float2(h2), f3 = __half22float2(h3);
            acc[0] += f0.x; acc[1] += f0.y; acc[2] += f1.x; acc[3] += f1.y;
            acc[4] += f2.x; acc[5] += f2.y; acc[6] += f3.x; acc[7] += f3.y;
        }
    }
    // remainder (0..3 edges)
    for (int jj = j + half; jj < end; jj += 2) {
        int c = g_adj[jj];
        uint4 p = __ldg(&sv[(size_t)c * 16 + hl]);
        __half2 h0 = *(__half2*)&p.x, h1 = *(__half2*)&p.y;
        __half2 h2 = *(__half2*)&p.z, h3 = *(__half2*)&p.w;
        float2 f0 = __half22float2(h0), f1 = __half22float2(h1);
        float2 f2 = __half22float2(h2), f3 = __half22float2(h3);
        acc[0] += f0.x; acc[1] += f0.y; acc[2] += f1.x; acc[3] += f1.y;
        acc[4] += f2.x; acc[5] += f2.y; acc[6] += f3.x; acc[7] += f3.y;
    }

    // combine the two half-warps
#pragma unroll
    for (int k = 0; k < 8; k++)
        acc[k] += __shfl_down_sync(0xffffffffu, acc[k], 16);

    if (half == 0) {
        float ds = g_dinv[warp];
        const float4* bp = (const float4*)(bias + hl * 8);
        float4 b0 = bp[0], b1 = bp[1];
        float4 o0, o1;
        o0.x = acc[0] * ds + b0.x;
        o0.y = acc[1] * ds + b0.y;
        o0.z = acc[2] * ds + b0.z;
        o0.w = acc[3] * ds + b0.w;
        o1.x = acc[4] * ds + b1.x;
        o1.y = acc[5] * ds + b1.y;
        o1.z = acc[6] * ds + b1.z;
        o1.w = acc[7] * ds + b1.w;
        float4* op = (float4*)(out + (size_t)warp * F + hl * 8);
        op[0] = o0;
        op[1] = o1;
    }
}

// ---------------- launch ----------------
extern "C" void kernel_launch(void* const* d_in, const int* in_sizes, int n_in,
                              void* d_out, int out_size)
{
    const float* x    = (const float*)d_in[0];
    const void*  ei   = d_in[1];
    const float* w    = (const float*)d_in[2];
    const float* bias = (const float*)d_in[3];
    float*       out  = (float*)d_out;

    int n = in_sizes[0] / F;
    int e = in_sizes[1] / 2;

    // slot 1
    prep_kernel<<<(n + 255) / 256, 256>>>((const unsigned int*)ei, w, n);
    // slot 2
    degree_kernel<<<(e + 255) / 256, 256>>>(ei, e);
    // slot 3
    scan_all_kernel<<<1, 1024>>>(n, e);
    // slot 4  (ncu profiles this one)
    size_t gemm_smem = (size_t)3 * 128 * APAD * sizeof(__half);  // 104448
    cudaFuncSetAttribute(gemm_tc_kernel,
                         cudaFuncAttributeMaxDynamicSharedMemorySize,
                         (int)gemm_smem);
    gemm_tc_kernel<<<(n + 127) / 128, 256, gemm_smem>>>(x, n);
    // slot 5
    scatter_kernel<<<(e + 255) / 256, 256>>>(ei, e);
    // slot 6
    int agg_blocks = (n * 32 + 255) / 256;
    aggregate_kernel<<<agg_blocks, 256>>>(out, bias, n);
}

// round 7
// speedup vs baseline: 1.1408x; 1.0005x over previous
#include <cuda_runtime.h>
#include <cuda_fp16.h>
#include <mma.h>
#include <stdint.h>

using namespace nvcuda;

#define N_NODES_MAX 100000
#define E_MAX       3200000
#define F           128

// ---------------- device scratch (static allocation only) ----------------
__device__ int     g_is64;
__device__ int     g_deg[N_NODES_MAX];
__device__ float   g_dinv[N_NODES_MAX];
__device__ int     g_rowptr[N_NODES_MAX + 1];
__device__ int     g_cursor[N_NODES_MAX];
__device__ int     g_adj[E_MAX];
__device__ __half  g_w16[F * F];                    // fp16 weight, 32 KB
__device__ __half2 g_sh[(size_t)N_NODES_MAX * 64];  // fp16 dinv-scaled support, 25.6 MB

__device__ __forceinline__ int get_idx(const void* ei, size_t pos) {
    if (g_is64) return (int)((const long long*)ei)[pos];
    return ((const int*)ei)[pos];
}

// ---------------- 1. prep: detect dtype + init deg + convert W ----------------
__global__ void prep_kernel(const unsigned int* __restrict__ raw,
                            const float* __restrict__ w, int n) {
    int i = blockIdx.x * blockDim.x + threadIdx.x;
    if (i < n) g_deg[i] = 1;                 // self loop
    if (i < F * F) g_w16[i] = __float2half_rn(w[i]);

    if (blockIdx.x == 0) {
        __shared__ int nonzero;
        if (threadIdx.x == 0) nonzero = 0;
        __syncthreads();
        int local = 0;
        for (int k = threadIdx.x; k < 2048; k += blockDim.x)
            if (raw[2 * k + 1] != 0u) local = 1;
        if (local) atomicOr(&nonzero, 1);
        __syncthreads();
        if (threadIdx.x == 0) g_is64 = (nonzero == 0) ? 1 : 0;
    }
}

// ---------------- 2. degree ----------------
__global__ void degree_kernel(const void* __restrict__ ei, int e) {
    int i = blockIdx.x * blockDim.x + threadIdx.x;
    if (i < e) atomicAdd(&g_deg[get_idx(ei, i)], 1);
}

// ---------------- 3. single-block chunked scan: rowptr/cursor/dinv ----------
__global__ void scan_all_kernel(int n, int e) {
    __shared__ int wsums[32];
    __shared__ int carry_s;
    int tid  = threadIdx.x;
    int wid  = tid >> 5;
    int lane = tid & 31;
    if (tid == 0) carry_s = 0;
    __syncthreads();

    for (int base = 0; base < n; base += 4096) {
        int v[4];
#pragma unroll
        for (int j = 0; j < 4; j++) {
            int idx = base + tid * 4 + j;
            if (idx < n) {
                int d = g_deg[idx];
                v[j] = d - 1;
                g_dinv[idx] = rsqrtf((float)d);
            } else v[j] = 0;
        }
        int s = v[0] + v[1] + v[2] + v[3];
        int x = s;
#pragma unroll
        for (int o = 1; o < 32; o <<= 1) {
            int y = __shfl_up_sync(0xffffffffu, x, o);
            if (lane >= o) x += y;
        }
        if (lane == 31) wsums[wid] = x;
        __syncthreads();
        if (tid < 32) {
            int wv = wsums[tid];
#pragma unroll
            for (int o = 1; o < 32; o <<= 1) {
                int y = __shfl_up_sync(0xffffffffu, wv, o);
                if (tid >= o) wv += y;
            }
            wsums[tid] = wv;  // inclusive
        }
        __syncthreads();

        int carry = carry_s;
        int excl = x - s + ((wid > 0) ? wsums[wid - 1] : 0) + carry;
        int run = excl;
#pragma unroll
        for (int j = 0; j < 4; j++) {
            int idx = base + tid * 4 + j;
            if (idx < n) { g_rowptr[idx] = run; g_cursor[idx] = run; }
            run += v[j];
        }
        __syncthreads();
        if (tid == 1023) carry_s = run;
        __syncthreads();
    }
    if (tid == 0) g_rowptr[n] = e;
}

// ---------------- 4. scatter (CSR adjacency fill)  -- profiled slot --------
__global__ void scatter_kernel(const void* __restrict__ ei, int e) {
    int i = blockIdx.x * blockDim.x + threadIdx.x;
    if (i < e) {
        int src = get_idx(ei, i);
        int dst = get_idx(ei, (size_t)e + i);
        int pos = atomicAdd(&g_cursor[src], 1);
        g_adj[pos] = dst;
    }
}

// ---------------- 5. tensor-core GEMM: g_sh = fp16((x @ W) * dinv[row]) -----
// x split hi+lo fp16 (two MMA passes). B resident in smem. 2 blocks/SM.
#define APAD 136   // half stride with padding

__global__ __launch_bounds__(256, 2) void gemm_tc_kernel(
    const float* __restrict__ x, int n)
{
    extern __shared__ char smem[];
    __half* Ahi = (__half*)smem;                 // [128][APAD]
    __half* Alo = Ahi + 128 * APAD;
    __half* Bs  = Alo + 128 * APAD;              // [128][APAD]
    float*  Cs  = (float*)smem;                  // epilogue reuse of Ahi+Alo

    int tid = threadIdx.x;
    int lane = tid & 31;
    int wid  = tid >> 5;
    int wm   = wid & 3;     // 0..3 -> M offset wm*32
    int wn   = wid >> 2;    // 0..1 -> N offset wn*64
    int block_row = blockIdx.x * 128;

    // load B into smem once
    {
        int r  = tid >> 1;
        int cb = (tid & 1) * 64;
        const uint4* src = (const uint4*)(g_w16 + r * F + cb);   // 8 x uint4
        uint4* dst = (uint4*)(Bs + r * APAD + cb);
#pragma unroll
        for (int k = 0; k < 8; k++) dst[k] = src[k];
    }

    // load A + hi/lo convert: 256 threads cover 128 rows x 128 cols
    int c4 = lane * 4;
#pragma unroll
    for (int i = 0; i < 16; i++) {
        int r  = wid + i * 8;    // 0..127 exactly once
        int gr = block_row + r;
        float4 v = make_float4(0.f, 0.f, 0.f, 0.f);
        if (gr < n) v = *(const float4*)(x + (size_t)gr * F + c4);
        __half h0 = __float2half_rn(v.x), h1 = __float2half_rn(v.y);
        __half h2 = __float2half_rn(v.z), h3 = __float2half_rn(v.w);
        Ahi[r * APAD + c4 + 0] = h0;
        Ahi[r * APAD + c4 + 1] = h1;
        Ahi[r * APAD + c4 + 2] = h2;
        Ahi[r * APAD + c4 + 3] = h3;
        Alo[r * APAD + c4 + 0] = __float2half_rn(v.x - __half2float(h0));
        Alo[r * APAD + c4 + 1] = __float2half_rn(v.y - __half2float(h1));
        Alo[r * APAD + c4 + 2] = __float2half_rn(v.z - __half2float(h2));
        Alo[r * APAD + c4 + 3] = __float2half_rn(v.w - __half2float(h3));
    }
    __syncthreads();

    wmma::fragment<wmma::accumulator, 16, 16, 16, float> acc[2][4];
#pragma unroll
    for (int mi = 0; mi < 2; mi++)
#pragma unroll
        for (int ni = 0; ni < 4; ni++) wmma::fill_fragment(acc[mi][ni], 0.0f);

#pragma unroll
    for (int k = 0; k < 8; k++) {
        wmma::fragment<wmma::matrix_b, 16, 16, 16, __half, wmma::row_major> bf[4];
#pragma unroll
        for (int ni = 0; ni < 4; ni++)
            wmma::load_matrix_sync(bf[ni], Bs + (k * 16) * APAD + wn * 64 + ni * 16, APAD);
#pragma unroll
        for (int pass = 0; pass < 2; pass++) {
            const __half* A = pass ? Alo : Ahi;
            wmma::fragment<wmma::matrix_a, 16, 16, 16, __half, wmma::row_major> af[2];
#pragma unroll
            for (int mi = 0; mi < 2; mi++)
                wmma::load_matrix_sync(af[mi], A + (wm * 32 + mi * 16) * APAD + k * 16, APAD);
#pragma unroll
            for (int mi = 0; mi < 2; mi++)
#pragma unroll
                for (int ni = 0; ni < 4; ni++)
                    wmma::mma_sync(acc[mi][ni], af[mi], bf[ni], acc[mi][ni]);
        }
    }
    __syncthreads();   // done reading A smem; reuse as float C

#pragma unroll
    for (int mi = 0; mi < 2; mi++)
#pragma unroll
        for (int ni = 0; ni < 4; ni++)
            wmma::store_matrix_sync(Cs + (wm * 32 + mi * 16) * APAD + wn * 64 + ni * 16,
                                    acc[mi][ni], APAD, wmma::mem_row_major);
    __syncthreads();

    // coalesced epilogue: warp owns 16 rows; scale row by dinv; fp16 store
    int wr = wid * 16;
#pragma unroll
    for (int rr = 0; rr < 16; rr++) {
        int r  = wr + rr;
        int gr = block_row + r;
        if (gr < n) {
            float d = g_dinv[gr];
            const float2* crow = (const float2*)(Cs + r * APAD);
            __half2* orow = g_sh + (size_t)gr * 64;
            float2 v0 = crow[lane];
            float2 v1 = crow[lane + 32];
            orow[lane]      = __floats2half2_rn(v0.x * d, v0.y * d);
            orow[lane + 32] = __floats2half2_rn(v1.x * d, v1.y * d);
        }
    }
}

// ---------------- 6. aggregation: one warp per node, uint2/lane, 8-wide -----
__global__ void aggregate_kernel(float* __restrict__ out,
                                 const float* __restrict__ bias, int n)
{
    int warp = (blockIdx.x * blockDim.x + threadIdx.x) >> 5;
    int lane = threadIdx.x & 31;
    if (warp >= n) return;

    const uint2* sv = (const uint2*)g_sh;   // row = 32 uint2 (256 B)

    uint2 p = __ldg(&sv[(size_t)warp * 32 + lane]);   // self loop
    float2 f0 = __half22float2(*(__half2*)&p.x), f1 = __half22float2(*(__half2*)&p.y);
    float4 acc = make_float4(f0.x, f0.y, f1.x, f1.y);

    int j   = g_rowptr[warp];
    int end = g_rowptr[warp + 1];

    // 8-wide unroll: 8 independent gathers in flight
    for (; j + 8 <= end; j += 8) {
        int c[8];
#pragma unroll
        for (int k = 0; k < 8; k++) c[k] = g_adj[j + k];
        uint2 pv[8];
#pragma unroll
        for (int k = 0; k < 8; k++) pv[k] = __ldg(&sv[(size_t)c[k] * 32 + lane]);
#pragma unroll
        for (int k = 0; k < 8; k++) {
            float2 q0 = __half22float2(*(__half2*)&pv[k].x);
            float2 q1 = __half22float2(*(__half2*)&pv[k].y);
            acc.x += q0.x; acc.y += q0.y; acc.z += q1.x; acc.w += q1.y;
        }
    }
    for (; j < end; j++) {
        int c = g_adj[j];
        uint2 pv = __ldg(&sv[(size_t)c * 32 + lane]);
        float2 q0 = __half22float2(*(__half2*)&pv.x), q1 = __half22float2(*(__half2*)&pv.y);
        acc.x += q0.x; acc.y += q0.y; acc.z += q1.x; acc.w += q1.y;
    }

    float d  = g_dinv[warp];
    float4 b = ((const float4*)bias)[lane];
    float4 o;
    o.x = acc.x * d + b.x;
    o.y = acc.y * d + b.y;
    o.z = acc.z * d + b.z;
    o.w = acc.w * d + b.w;
    ((float4*)out)[(size_t)warp * 32 + lane] = o;
}

// ---------------- launch ----------------
extern "C" void kernel_launch(void* const* d_in, const int* in_sizes, int n_in,
                              void* d_out, int out_size)
{
    const float* x    = (const float*)d_in[0];
    const void*  ei   = d_in[1];
    const float* w    = (const float*)d_in[2];
    const float* bias = (const float*)d_in[3];
    float*       out  = (float*)d_out;

    int n = in_sizes[0] / F;
    int e = in_sizes[1] / 2;

    // slot 1
    prep_kernel<<<(n + 255) / 256, 256>>>((const unsigned int*)ei, w, n);
    // slot 2
    degree_kernel<<<(e + 255) / 256, 256>>>(ei, e);
    // slot 3
    scan_all_kernel<<<1, 1024>>>(n, e);
    // slot 4  (ncu profiles this slot)
    scatter_kernel<<<(e + 255) / 256, 256>>>(ei, e);
    // slot 5
    size_t gemm_smem = (size_t)3 * 128 * APAD * sizeof(__half);  // 104448
    cudaFuncSetAttribute(gemm_tc_kernel,
                         cudaFuncAttributeMaxDynamicSharedMemorySize,
                         (int)gemm_smem);
    gemm_tc_kernel<<<(n + 127) / 128, 256, gemm_smem>>>(x, n);
    // slot 6
    int agg_blocks = (n * 32 + 255) / 256;
    aggregate_kernel<<<agg_blocks, 256>>>(out, bias, n);
}

// round 8
// speedup vs baseline: 1.5776x; 1.3828x over previous
#include <cuda_runtime.h>
#include <cuda_fp16.h>
#include <mma.h>
#include <stdint.h>

using namespace nvcuda;

#define N_NODES_MAX 100000
#define E_MAX       3200000
#define F           128

// ---------------- device scratch (static allocation only) ----------------
__device__ int     g_is64;
__device__ int     g_deg[N_NODES_MAX];
__device__ float   g_dinv[N_NODES_MAX];
__device__ int     g_rowptr[N_NODES_MAX + 1];
__device__ int     g_cursor[N_NODES_MAX];
__device__ int     g_adj[E_MAX];
__device__ int     g_bsums[256];
__device__ int     g_bscan[256];
__device__ __half  g_w16[F * F];                    // fp16 weight, 32 KB
__device__ __half2 g_sh[(size_t)N_NODES_MAX * 64];  // fp16 dinv-scaled support, 25.6 MB

__device__ __forceinline__ int get_idx(const void* ei, size_t pos) {
    if (g_is64) return (int)((const long long*)ei)[pos];
    return ((const int*)ei)[pos];
}

// ---------------- 1. prep: detect dtype + init deg + convert W --------------
__global__ void prep_kernel(const unsigned int* __restrict__ raw,
                            const float* __restrict__ w, int n) {
    int i = blockIdx.x * blockDim.x + threadIdx.x;
    if (i < n) g_deg[i] = 1;                 // self loop
    if (i < F * F) g_w16[i] = __float2half_rn(w[i]);

    if (blockIdx.x == 0) {
        __shared__ int nonzero;
        if (threadIdx.x == 0) nonzero = 0;
        __syncthreads();
        int local = 0;
        for (int k = threadIdx.x; k < 2048; k += blockDim.x)
            if (raw[2 * k + 1] != 0u) local = 1;
        if (local) atomicOr(&nonzero, 1);
        __syncthreads();
        if (threadIdx.x == 0) g_is64 = (nonzero == 0) ? 1 : 0;
    }
}

// ---------------- 2. degree ----------------
__global__ void degree_kernel(const void* __restrict__ ei, int e) {
    int i = blockIdx.x * blockDim.x + threadIdx.x;
    if (i < e) atomicAdd(&g_deg[get_idx(ei, i)], 1);
}

// ---------------- 3. multi-block scan chain (R4-proven, ~8us total) --------
// per-block exclusive scan over 1024 elements (256 thr x 4); also writes dinv
__global__ void scan_local_kernel(int n) {
    __shared__ int wsum[8];
    int tid  = threadIdx.x;
    int base = blockIdx.x * 1024 + tid * 4;
    int v[4];
#pragma unroll
    for (int j = 0; j < 4; j++) {
        int idx = base + j;
        if (idx < n) {
            int d = g_deg[idx];
            v[j] = d - 1;
            g_dinv[idx] = rsqrtf((float)d);
        } else v[j] = 0;
    }
    int s = v[0] + v[1] + v[2] + v[3];
    int x = s;
#pragma unroll
    for (int o = 1; o < 32; o <<= 1) {
        int y = __shfl_up_sync(0xffffffffu, x, o);
        if ((tid & 31) >= o) x += y;
    }
    if ((tid & 31) == 31) wsum[tid >> 5] = x;
    __syncthreads();
    if (tid < 8) {
        int w = wsum[tid];
#pragma unroll
        for (int o = 1; o < 8; o <<= 1) {
            int y = __shfl_up_sync(0xffu, w, o);
            if (tid >= o) w += y;
        }
        wsum[tid] = w;  // inclusive warp sums
    }
    __syncthreads();
    int excl = x - s + ((tid >= 32) ? wsum[(tid >> 5) - 1] : 0);
    int run = excl;
#pragma unroll
    for (int j = 0; j < 4; j++) {
        int idx = base + j;
        if (idx < n) g_rowptr[idx] = run;
        run += v[j];
    }
    if (tid == 255) g_bsums[blockIdx.x] = run;
}

// ---------------- 4. tensor-core GEMM (profiled slot): needs only dinv ------
// x split hi+lo fp16 (two MMA passes). B resident in smem. 2 blocks/SM.
#define APAD 136   // half stride with padding

__global__ __launch_bounds__(256, 2) void gemm_tc_kernel(
    const float* __restrict__ x, int n)
{
    extern __shared__ char smem[];
    __half* Ahi = (__half*)smem;                 // [128][APAD]
    __half* Alo = Ahi + 128 * APAD;
    __half* Bs  = Alo + 128 * APAD;              // [128][APAD]
    float*  Cs  = (float*)smem;                  // epilogue reuse of Ahi+Alo

    int tid = threadIdx.x;
    int lane = tid & 31;
    int wid  = tid >> 5;
    int wm   = wid & 3;     // 0..3 -> M offset wm*32
    int wn   = wid >> 2;    // 0..1 -> N offset wn*64
    int block_row = blockIdx.x * 128;

    // load B into smem once
    {
        int r  = tid >> 1;
        int cb = (tid & 1) * 64;
        const uint4* src = (const uint4*)(g_w16 + r * F + cb);   // 8 x uint4
        uint4* dst = (uint4*)(Bs + r * APAD + cb);
#pragma unroll
        for (int k = 0; k < 8; k++) dst[k] = src[k];
    }

    // load A + hi/lo convert: 256 threads cover 128 rows x 128 cols
    int c4 = lane * 4;
#pragma unroll
    for (int i = 0; i < 16; i++) {
        int r  = wid + i * 8;    // 0..127 exactly once
        int gr = block_row + r;
        float4 v = make_float4(0.f, 0.f, 0.f, 0.f);
        if (gr < n) v = *(const float4*)(x + (size_t)gr * F + c4);
        __half h0 = __float2half_rn(v.x), h1 = __float2half_rn(v.y);
        __half h2 = __float2half_rn(v.z), h3 = __float2half_rn(v.w);
        Ahi[r * APAD + c4 + 0] = h0;
        Ahi[r * APAD + c4 + 1] = h1;
        Ahi[r * APAD + c4 + 2] = h2;
        Ahi[r * APAD + c4 + 3] = h3;
        Alo[r * APAD + c4 + 0] = __float2half_rn(v.x - __half2float(h0));
        Alo[r * APAD + c4 + 1] = __float2half_rn(v.y - __half2float(h1));
        Alo[r * APAD + c4 + 2] = __float2half_rn(v.z - __half2float(h2));
        Alo[r * APAD + c4 + 3] = __float2half_rn(v.w - __half2float(h3));
    }
    __syncthreads();

    wmma::fragment<wmma::accumulator, 16, 16, 16, float> acc[2][4];
#pragma unroll
    for (int mi = 0; mi < 2; mi++)
#pragma unroll
        for (int ni = 0; ni < 4; ni++) wmma::fill_fragment(acc[mi][ni], 0.0f);

#pragma unroll
    for (int k = 0; k < 8; k++) {
        wmma::fragment<wmma::matrix_b, 16, 16, 16, __half, wmma::row_major> bf[4];
#pragma unroll
        for (int ni = 0; ni < 4; ni++)
            wmma::load_matrix_sync(bf[ni], Bs + (k * 16) * APAD + wn * 64 + ni * 16, APAD);
#pragma unroll
        for (int pass = 0; pass < 2; pass++) {
            const __half* A = pass ? Alo : Ahi;
            wmma::fragment<wmma::matrix_a, 16, 16, 16, __half, wmma::row_major> af[2];
#pragma unroll
            for (int mi = 0; mi < 2; mi++)
                wmma::load_matrix_sync(af[mi], A + (wm * 32 + mi * 16) * APAD + k * 16, APAD);
#pragma unroll
            for (int mi = 0; mi < 2; mi++)
#pragma unroll
                for (int ni = 0; ni < 4; ni++)
                    wmma::mma_sync(acc[mi][ni], af[mi], bf[ni], acc[mi][ni]);
        }
    }
    __syncthreads();   // done reading A smem; reuse as float C

#pragma unroll
    for (int mi = 0; mi < 2; mi++)
#pragma unroll
        for (int ni = 0; ni < 4; ni++)
            wmma::store_matrix_sync(Cs + (wm * 32 + mi * 16) * APAD + wn * 64 + ni * 16,
                                    acc[mi][ni], APAD, wmma::mem_row_major);
    __syncthreads();

    // coalesced epilogue: warp owns 16 rows; scale row by dinv; fp16 store
    int wr = wid * 16;
#pragma unroll
    for (int rr = 0; rr < 16; rr++) {
        int r  = wr + rr;
        int gr = block_row + r;
        if (gr < n) {
            float d = g_dinv[gr];
            const float2* crow = (const float2*)(Cs + r * APAD);
            __half2* orow = g_sh + (size_t)gr * 64;
            float2 v0 = crow[lane];
            float2 v1 = crow[lane + 32];
            orow[lane]      = __floats2half2_rn(v0.x * d, v0.y * d);
            orow[lane + 32] = __floats2half2_rn(v1.x * d, v1.y * d);
        }
    }
}

// ---------------- 5. scan chain tail --------------------------------------
__global__ void scan_bsums_kernel(int nb) {
    __shared__ int sh[128];
    int tid = threadIdx.x;
    int v = (tid < nb) ? g_bsums[tid] : 0;
    sh[tid] = v;
    __syncthreads();
#pragma unroll
    for (int o = 1; o < 128; o <<= 1) {
        int t = sh[tid];
        int y = (tid >= o) ? sh[tid - o] : 0;
        __syncthreads();
        sh[tid] = t + y;
        __syncthreads();
    }
    g_bscan[tid] = sh[tid] - v;  // exclusive
}

__global__ void add_offsets_kernel(int n, int e) {
    int i = blockIdx.x * blockDim.x + threadIdx.x;
    if (i < n) {
        int r = g_rowptr[i] + g_bscan[i >> 10];
        g_rowptr[i] = r;
        g_cursor[i] = r;
    }
    if (i == 0) g_rowptr[n] = e;
}

// ---------------- 6. scatter (CSR adjacency fill) ----------------
__global__ void scatter_kernel(const void* __restrict__ ei, int e) {
    int i = blockIdx.x * blockDim.x + threadIdx.x;
    if (i < e) {
        int src = get_idx(ei, i);
        int dst = get_idx(ei, (size_t)e + i);
        int pos = atomicAdd(&g_cursor[src], 1);
        g_adj[pos] = dst;
    }
}

// ---------------- 7. aggregation: one warp per node, uint2/lane, 4-wide -----
__global__ void aggregate_kernel(float* __restrict__ out,
                                 const float* __restrict__ bias, int n)
{
    int warp = (blockIdx.x * blockDim.x + threadIdx.x) >> 5;
    int lane = threadIdx.x & 31;
    if (warp >= n) return;

    const uint2* sv = (const uint2*)g_sh;   // row = 32 uint2 (256 B)

    uint2 p = __ldg(&sv[(size_t)warp * 32 + lane]);   // self loop
    float2 f0 = __half22float2(*(__half2*)&p.x), f1 = __half22float2(*(__half2*)&p.y);
    float4 acc = make_float4(f0.x, f0.y, f1.x, f1.y);

    int j   = g_rowptr[warp];
    int end = g_rowptr[warp + 1];

    for (; j + 3 < end; j += 4) {
        int c0 = g_adj[j + 0];
        int c1 = g_adj[j + 1];
        int c2 = g_adj[j + 2];
        int c3 = g_adj[j + 3];
        uint2 p0 = __ldg(&sv[(size_t)c0 * 32 + lane]);
        uint2 p1 = __ldg(&sv[(size_t)c1 * 32 + lane]);
        uint2 p2 = __ldg(&sv[(size_t)c2 * 32 + lane]);
        uint2 p3 = __ldg(&sv[(size_t)c3 * 32 + lane]);
        float2 q0 = __half22float2(*(__half2*)&p0.x), q1 = __half22float2(*(__half2*)&p0.y);
        float2 q2 = __half22float2(*(__half2*)&p1.x), q3 = __half22float2(*(__half2*)&p1.y);
        float2 q4 = __half22float2(*(__half2*)&p2.x), q5 = __half22float2(*(__half2*)&p2.y);
        float2 q6 = __half22float2(*(__half2*)&p3.x), q7 = __half22float2(*(__half2*)&p3.y);
        acc.x += (q0.x + q2.x) + (q4.x + q6.x);
        acc.y += (q0.y + q2.y) + (q4.y + q6.y);
        acc.z += (q1.x + q3.x) + (q5.x + q7.x);
        acc.w += (q1.y + q3.y) + (q5.y + q7.y);
    }
    for (; j < end; j++) {
        int c = g_adj[j];
        uint2 pv = __ldg(&sv[(size_t)c * 32 + lane]);
        float2 q0 = __half22float2(*(__half2*)&pv.x), q1 = __half22float2(*(__half2*)&pv.y);
        acc.x += q0.x; acc.y += q0.y; acc.z += q1.x; acc.w += q1.y;
    }

    float d  = g_dinv[warp];
    float4 b = ((const float4*)bias)[lane];
    float4 o;
    o.x = acc.x * d + b.x;
    o.y = acc.y * d + b.y;
    o.z = acc.z * d + b.z;
    o.w = acc.w * d + b.w;
    ((float4*)out)[(size_t)warp * 32 + lane] = o;
}

// ---------------- launch ----------------
extern "C" void kernel_launch(void* const* d_in, const int* in_sizes, int n_in,
                              void* d_out, int out_size)
{
    const float* x    = (const float*)d_in[0];
    const void*  ei   = d_in[1];
    const float* w    = (const float*)d_in[2];
    const float* bias = (const float*)d_in[3];
    float*       out  = (float*)d_out;

    int n = in_sizes[0] / F;
    int e = in_sizes[1] / 2;

    int nb = (n + 1023) / 1024;   // <=128

    // slot 1
    prep_kernel<<<(n + 255) / 256, 256>>>((const unsigned int*)ei, w, n);
    // slot 2
    degree_kernel<<<(e + 255) / 256, 256>>>(ei, e);
    // slot 3: local scan also produces full dinv
    scan_local_kernel<<<nb, 256>>>(n);
    // slot 4 (ncu profiles this): gemm only needs dinv
    size_t gemm_smem = (size_t)3 * 128 * APAD * sizeof(__half);  // 104448
    cudaFuncSetAttribute(gemm_tc_kernel,
                         cudaFuncAttributeMaxDynamicSharedMemorySize,
                         (int)gemm_smem);
    gemm_tc_kernel<<<(n + 127) / 128, 256, gemm_smem>>>(x, n);
    // slots 5-6: finish rowptr/cursor
    scan_bsums_kernel<<<1, 128>>>(nb);
    add_offsets_kernel<<<(n + 255) / 256, 256>>>(n, e);
    // slot 7
    scatter_kernel<<<(e + 255) / 256, 256>>>(ei, e);
    // slot 8
    int agg_blocks = (n * 32 + 255) / 256;
    aggregate_kernel<<<agg_blocks, 256>>>(out, bias, n);
}